// round 13
// baseline (speedup 1.0000x reference)
#include <cuda_runtime.h>
#include <cuda_bf16.h>
#include <cstdint>
#include <cstddef>

#define B_   4
#define C_   512
#define N_   4096
#define CQ_  64
#define SCALE_ 0.125f   // (C/8)^-0.5

// ---------------- device scratch (single bf16) ----------
__device__ __nv_bfloat16 g_q[B_ * CQ_ * N_];                  // [b][q][n]
__device__ __nv_bfloat16 g_k[B_ * CQ_ * N_];
__device__ __nv_bfloat16 g_v[(size_t)B_ * C_ * N_];           // [b][c][n]
__device__ __nv_bfloat16 g_p[(size_t)B_ * N_ * N_];           // exp(E) [b][i][j]
__device__ __nv_bfloat16 g_xs[(size_t)B_ * C_ * N_];          // x bf16
__device__ __nv_bfloat16 g_xt[(size_t)B_ * C_ * N_];
__device__ __nv_bfloat16 g_ws[C_ * C_], g_wt[C_ * C_];        // Wvs/Wvt bf16 [c][k]
__device__ float g_psum[B_ * 16 * N_];                        // [b][jt][i]
__device__ float g_inv[B_ * N_];

#define LD8(dst, ptr)                                              \
    do {                                                           \
        float4 _u0 = *(const float4*)((ptr));                      \
        float4 _u1 = *(const float4*)((ptr) + 4);                  \
        (dst)[0]=_u0.x; (dst)[1]=_u0.y; (dst)[2]=_u0.z; (dst)[3]=_u0.w; \
        (dst)[4]=_u1.x; (dst)[5]=_u1.y; (dst)[6]=_u1.z; (dst)[7]=_u1.w; \
    } while (0)

// ====================== helpers ======================
__device__ __forceinline__ uint32_t smem_u32(const void* p) {
    uint32_t a;
    asm("{ .reg .u64 t; cvta.to.shared.u64 t, %1; cvt.u32.u64 %0, t; }" : "=r"(a) : "l"(p));
    return a;
}
__device__ __forceinline__ void cp16(uint32_t dst, const void* src) {
    asm volatile("cp.async.cg.shared.global [%0], [%1], 16;" :: "r"(dst), "l"(src));
}
#define CP_COMMIT() asm volatile("cp.async.commit_group;" ::: "memory")
#define CP_WAIT(n)  asm volatile("cp.async.wait_group %0;" :: "n"(n) : "memory")
__device__ __forceinline__ void ldm_x4(uint32_t* r, uint32_t addr) {
    asm volatile("ldmatrix.sync.aligned.m8n8.x4.shared.b16 {%0,%1,%2,%3}, [%4];"
        : "=r"(r[0]), "=r"(r[1]), "=r"(r[2]), "=r"(r[3]) : "r"(addr));
}
__device__ __forceinline__ void ldm_x4t(uint32_t* r, uint32_t addr) {
    asm volatile("ldmatrix.sync.aligned.m8n8.x4.trans.shared.b16 {%0,%1,%2,%3}, [%4];"
        : "=r"(r[0]), "=r"(r[1]), "=r"(r[2]), "=r"(r[3]) : "r"(addr));
}
__device__ __forceinline__ void mma16816(float* c, const uint32_t* a, uint32_t b0, uint32_t b1) {
    asm volatile(
        "mma.sync.aligned.m16n8k16.row.col.f32.bf16.bf16.f32 "
        "{%0,%1,%2,%3}, {%4,%5,%6,%7}, {%8,%9}, {%0,%1,%2,%3};"
        : "+f"(c[0]), "+f"(c[1]), "+f"(c[2]), "+f"(c[3])
        : "r"(a[0]), "r"(a[1]), "r"(a[2]), "r"(a[3]), "r"(b0), "r"(b1));
}
__device__ __forceinline__ uint32_t pack2f(float a, float b) {
    __nv_bfloat162 t; t.x = __float2bfloat16(a); t.y = __float2bfloat16(b);
    return *(uint32_t*)&t;
}
__device__ __forceinline__ void bulk128(uint32_t dst, const void* src, uint32_t mbar) {
    asm volatile(
        "cp.async.bulk.shared::cluster.global.mbarrier::complete_tx::bytes [%0], [%1], 128, [%2];"
        :: "r"(dst), "l"(src), "r"(mbar) : "memory");
}
#define MBARRIER_INIT(mb, cnt) \
    asm volatile("mbarrier.init.shared.b64 [%0], %1;" :: "r"((uint32_t)(mb)), "r"((uint32_t)(cnt)) : "memory")
#define MBARRIER_EXPECT_TX(mb, bytes) \
    asm volatile("mbarrier.arrive.expect_tx.shared.b64 _, [%0], %1;" \
        :: "r"((uint32_t)(mb)), "r"((uint32_t)(bytes)) : "memory")
#define MBARRIER_WAIT_PARITY(mb, par) do { \
    uint32_t _mb = (uint32_t)(mb); uint32_t _p = (uint32_t)(par); uint32_t _done; \
    asm volatile("{\n\t.reg .pred p;\n\t" \
        "mbarrier.try_wait.parity.acquire.cta.shared::cta.b64 p, [%1], %2;\n\t" \
        "selp.b32 %0, 1, 0, p;\n\t}" : "=r"(_done) : "r"(_mb), "r"(_p) : "memory"); \
    if (!_done) { \
        asm volatile("{\n\t.reg .pred P1;\n\t" \
            "WL_%=:\n\t" \
            "mbarrier.try_wait.parity.acquire.cta.shared::cta.b64 P1, [%0], %1, 0x989680;\n\t" \
            "@P1 bra.uni WD_%=;\n\t" \
            "bra.uni WL_%=;\n\t" \
            "WD_%=:\n\t}" :: "r"(_mb), "r"(_p) : "memory"); \
    } \
} while (0)

// ---------------------------------------------------------------------------
// W convert: fp32 -> bf16
// ---------------------------------------------------------------------------
__global__ __launch_bounds__(256) void w_cvt_kernel(
    const float* __restrict__ Wvs, const float* __restrict__ Wvt)
{
    const size_t idx4 = ((size_t)blockIdx.x * 256 + threadIdx.x) * 4;
    const float* src = blockIdx.y ? Wvt : Wvs;
    __nv_bfloat16* dst = blockIdx.y ? g_wt : g_ws;
    float4 v = *(const float4*)(src + idx4);
    uint32_t* p = (uint32_t*)(dst + idx4);
    p[0] = pack2f(v.x, v.y);
    p[1] = pack2f(v.z, v.w);
}

// ---------------------------------------------------------------------------
// Q/K projection fp32 -> bf16 out + x bf16 convert (from smem tile).
// ---------------------------------------------------------------------------
__global__ __launch_bounds__(256, 2) void qk_proj_kernel(
    const float* __restrict__ Wq, const float* __restrict__ bq,
    const float* __restrict__ Wk, const float* __restrict__ bk,
    const float* __restrict__ xs, const float* __restrict__ xt)
{
    __shared__ float Ws[32][68];
    __shared__ float Xs[32][128];

    const int which = blockIdx.z;
    const int b  = blockIdx.y;
    const int n0 = blockIdx.x * 128;
    const float* W = which ? Wk : Wq;
    const float* bias = which ? bk : bq;
    const float* Xb = (which ? xt : xs) + (size_t)b * C_ * N_;
    __nv_bfloat16* Y = which ? g_k : g_q;
    __nv_bfloat16* Xdst = (which ? g_xt : g_xs) + (size_t)b * C_ * N_;

    const int tid = threadIdx.x;
    const int tx = tid & 15;
    const int ty = tid >> 4;

    float acc[4][8];
#pragma unroll
    for (int i = 0; i < 4; i++)
#pragma unroll
        for (int j = 0; j < 8; j++) acc[i][j] = 0.f;

    for (int k0 = 0; k0 < C_; k0 += 32) {
#pragma unroll
        for (int r = 0; r < 8; r++) {
            int idx = tid + r * 256;
            int m = idx >> 5, kk = idx & 31;
            Ws[kk][m] = W[(size_t)m * C_ + k0 + kk];
        }
#pragma unroll
        for (int r = 0; r < 16; r++) {
            int idx = tid + r * 256;
            int kk = idx >> 7, n = idx & 127;
            Xs[kk][n] = Xb[(size_t)(k0 + kk) * N_ + n0 + n];
        }
        __syncthreads();

#pragma unroll
        for (int r = 0; r < 8; r++) {
            int idx = tid + r * 256;
            int kk = idx >> 6, np = idx & 63;
            *(uint32_t*)(Xdst + (size_t)(k0 + kk) * N_ + n0 + np * 2) =
                pack2f(Xs[kk][np * 2], Xs[kk][np * 2 + 1]);
        }

#pragma unroll
        for (int kk = 0; kk < 32; kk++) {
            float a[4], bb[8];
#pragma unroll
            for (int i = 0; i < 4; i++) a[i] = Ws[kk][ty * 4 + i];
            LD8(bb, &Xs[kk][tx * 8]);
#pragma unroll
            for (int i = 0; i < 4; i++)
#pragma unroll
                for (int j = 0; j < 8; j++) acc[i][j] += a[i] * bb[j];
        }
        __syncthreads();
    }
#pragma unroll
    for (int i = 0; i < 4; i++) {
        int m = ty * 4 + i;
        float bv = bias[m];
        uint32_t* yp = (uint32_t*)(Y + ((size_t)b * CQ_ + m) * N_ + n0 + tx * 8);
#pragma unroll
        for (int p = 0; p < 4; p++)
            yp[p] = pack2f(acc[i][2*p] + bv, acc[i][2*p+1] + bv);
    }
}

// ---------------------------------------------------------------------------
// V projection (512 thr): unchanged (cp.async, 4 stages)
// ---------------------------------------------------------------------------
#define VP_AROW 80
#define VP_BROW 528
#define VP_AMAT (128 * VP_AROW)
#define VP_BMAT (32 * VP_BROW)
#define VP_WS 0
#define VP_WT VP_AMAT
#define VP_XS (2 * VP_AMAT)
#define VP_XT (2 * VP_AMAT + VP_BMAT)
#define VP_STAGE (2 * VP_AMAT + 2 * VP_BMAT)   // 54272
#define VP_SMEM (4 * VP_STAGE + 1024)          // 218112

__device__ __forceinline__ void vp_load_stage(uint32_t sb, int b, int c0, int n0, int k0, int tid)
{
#pragma unroll
    for (int k = 0; k < 2; k++) {
        int idx = tid + k * 512;
        int mat = idx >> 9, rem = idx & 511;
        int r = rem >> 2, ch = rem & 3;
        const __nv_bfloat16* src = mat ? g_wt : g_ws;
        cp16(sb + mat * VP_AMAT + r * VP_AROW + ch * 16,
             src + (size_t)(c0 + r) * C_ + k0 + ch * 8);
    }
#pragma unroll
    for (int k = 0; k < 4; k++) {
        int idx = tid + k * 512;
        int mat = idx >> 10, rem = idx & 1023;
        int r = rem >> 5, ch = rem & 31;
        const __nv_bfloat16* src = mat ? g_xt : g_xs;
        cp16(sb + 2 * VP_AMAT + mat * VP_BMAT + r * VP_BROW + ch * 16,
             src + ((size_t)b * C_ + k0 + r) * N_ + n0 + ch * 8);
    }
    CP_COMMIT();
}

__global__ __launch_bounds__(512, 1) void v_proj_mma_kernel(
    const float* __restrict__ bvs, const float* __restrict__ bvt)
{
    extern __shared__ char dsm[];
    uint32_t raw  = smem_u32(dsm);
    uint32_t base = (raw + 1023) & ~1023u;

    const int tid = threadIdx.x;
    const int lane = tid & 31;
    const int wid = tid >> 5;
    const int warp_m = wid & 3;
    const int warp_n = wid >> 2;

    const int b  = blockIdx.z;
    const int c0 = blockIdx.y * 128;
    const int n0 = blockIdx.x * 256;

    float acc[2][8][4];
#pragma unroll
    for (int mt = 0; mt < 2; mt++)
#pragma unroll
        for (int t = 0; t < 8; t++)
#pragma unroll
            for (int q = 0; q < 4; q++) acc[mt][t][q] = 0.f;

    vp_load_stage(base,                b, c0, n0, 0,  tid);
    vp_load_stage(base + VP_STAGE,     b, c0, n0, 32, tid);
    vp_load_stage(base + 2 * VP_STAGE, b, c0, n0, 64, tid);

    const uint32_t a_lrow = (uint32_t)(warp_m * 32 + (lane & 15));
    const uint32_t a_lcol = (uint32_t)((lane >> 4) * 16);
    const uint32_t b_lrow = (uint32_t)((lane & 7) | (lane & 8));
    const uint32_t b_lcol = (uint32_t)((warp_n * 64 + ((lane >> 4) & 1) * 8) * 2);

    for (int chk = 0; chk < 16; chk++) {
        const uint32_t sb = base + (chk & 3) * VP_STAGE;
        if (chk <= 13)      CP_WAIT(2);
        else if (chk == 14) CP_WAIT(1);
        else                CP_WAIT(0);
        __syncthreads();
        if (chk + 3 < 16)
            vp_load_stage(base + ((chk + 3) & 3) * VP_STAGE, b, c0, n0, (chk + 3) * 32, tid);

#pragma unroll
        for (int ks = 0; ks < 2; ks++) {
            uint32_t ws[2][4], wt[2][4];
#pragma unroll
            for (int mt = 0; mt < 2; mt++) {
                uint32_t aoff = (a_lrow + mt * 16) * VP_AROW + a_lcol + ks * 32;
                ldm_x4(ws[mt], sb + VP_WS + aoff);
                ldm_x4(wt[mt], sb + VP_WT + aoff);
            }
#pragma unroll
            for (int ng = 0; ng < 4; ng++) {
                uint32_t boff = (b_lrow + ks * 16) * VP_BROW + b_lcol + ng * 32;
                uint32_t xsf[4], xtf[4];
                ldm_x4t(xsf, sb + VP_XS + boff);
                ldm_x4t(xtf, sb + VP_XT + boff);
#pragma unroll
                for (int mt = 0; mt < 2; mt++)
#pragma unroll
                    for (int sub = 0; sub < 2; sub++) {
                        float* a = acc[mt][ng * 2 + sub];
                        uint32_t s0 = sub ? xsf[2] : xsf[0], s1 = sub ? xsf[3] : xsf[1];
                        uint32_t t0 = sub ? xtf[2] : xtf[0], t1 = sub ? xtf[3] : xtf[1];
                        mma16816(a, ws[mt], s0, s1);
                        mma16816(a, wt[mt], t0, t1);
                    }
            }
        }
    }

    const int gp = lane >> 2, tg = lane & 3;
#pragma unroll
    for (int mt = 0; mt < 2; mt++) {
        const int r0 = c0 + warp_m * 32 + mt * 16 + gp;
        const float bv0 = bvs[r0] + bvt[r0];
        const float bv1 = bvs[r0 + 8] + bvt[r0 + 8];
#pragma unroll
        for (int t = 0; t < 8; t++) {
            const int nc = n0 + warp_n * 64 + t * 8 + tg * 2;
            size_t i0 = ((size_t)b * C_ + r0) * N_ + nc;
            size_t i1 = i0 + 8 * (size_t)N_;
            *(uint32_t*)(g_v + i0) = pack2f(acc[mt][t][0] + bv0, acc[mt][t][1] + bv0);
            *(uint32_t*)(g_v + i1) = pack2f(acc[mt][t][2] + bv1, acc[mt][t][3] + bv1);
        }
    }
}

// ---------------------------------------------------------------------------
// Energy + exp (512 thr): unchanged
// ---------------------------------------------------------------------------
#define EQ_ROW 272
#define EK_ROW 528
#define EN_Q 0
#define EN_QB (CQ_ * EQ_ROW)          // 17408
#define EN_K EN_QB
#define EN_KB (CQ_ * EK_ROW)          // 33792
#define EN_STG (EN_QB + EN_KB)        // 51200
#define EN_STG_STRIDE 132
#define EN_STG_BYTES (128 * EN_STG_STRIDE * 4)
#define EN_PS (EN_STG + EN_STG_BYTES)
#define EN_SMEM (EN_PS + 2048 + 1024)

__global__ __launch_bounds__(512, 1) void energy_exp_kernel()
{
    extern __shared__ char dsm[];
    uint32_t raw  = smem_u32(dsm);
    uint32_t base = (raw + 1023) & ~1023u;
    char* cbase = dsm + (base - raw);
    float* ps = (float*)(cbase + EN_PS);
    uint32_t* pstg = (uint32_t*)(cbase + EN_STG);

    const int tid = threadIdx.x;
    const int lane = tid & 31;
    const int wid = tid >> 5;
    const int warp_m = wid & 3;
    const int warp_n = wid >> 2;

    const int b  = blockIdx.z;
    const int i0 = blockIdx.y * 128;
    const int jt = blockIdx.x;
    const int j0 = jt * 256;

#pragma unroll
    for (int k = 0; k < 2; k++) {
        int idx = tid + k * 512;
        int r = idx >> 4, ch = idx & 15;
        cp16(base + EN_Q + r * EQ_ROW + ch * 16,
             g_q + ((size_t)b * CQ_ + r) * N_ + i0 + ch * 8);
    }
#pragma unroll
    for (int k = 0; k < 4; k++) {
        int idx = tid + k * 512;
        int r = idx >> 5, ch = idx & 31;
        cp16(base + EN_K + r * EK_ROW + ch * 16,
             g_k + ((size_t)b * CQ_ + r) * N_ + j0 + ch * 8);
    }
    CP_COMMIT();
    CP_WAIT(0);
    __syncthreads();

    float acc[2][8][4];
#pragma unroll
    for (int mt = 0; mt < 2; mt++)
#pragma unroll
        for (int t = 0; t < 8; t++)
#pragma unroll
            for (int q = 0; q < 4; q++) acc[mt][t][q] = 0.f;

    const uint32_t aq_row = (uint32_t)((lane & 7) | ((lane >> 4) << 3));
    const uint32_t aq_col = (uint32_t)((warp_m * 32 + ((lane >> 3) & 1) * 8) * 2);
    const uint32_t bk_row = (uint32_t)((lane & 7) | (lane & 8));
    const uint32_t bk_col = (uint32_t)((warp_n * 64 + ((lane >> 4) & 1) * 8) * 2);

#pragma unroll
    for (int ks = 0; ks < 4; ks++) {
        uint32_t ah[2][4];
#pragma unroll
        for (int mt = 0; mt < 2; mt++) {
            uint32_t aoff = (aq_row + ks * 16) * EQ_ROW + aq_col + mt * 32;
            ldm_x4t(ah[mt], base + EN_Q + aoff);
        }
#pragma unroll
        for (int ng = 0; ng < 4; ng++) {
            uint32_t boff = (bk_row + ks * 16) * EK_ROW + bk_col + ng * 32;
            uint32_t bh[4];
            ldm_x4t(bh, base + EN_K + boff);
#pragma unroll
            for (int mt = 0; mt < 2; mt++)
#pragma unroll
                for (int sub = 0; sub < 2; sub++) {
                    float* a = acc[mt][ng * 2 + sub];
                    uint32_t p0 = sub ? bh[2] : bh[0], p1 = sub ? bh[3] : bh[1];
                    mma16816(a, ah[mt], p0, p1);
                }
        }
    }

    const int gp = lane >> 2, tg = lane & 3;
    float rs[2][2] = {{0.f, 0.f}, {0.f, 0.f}};
#pragma unroll
    for (int mt = 0; mt < 2; mt++) {
        const int il = warp_m * 32 + mt * 16 + gp;
#pragma unroll
        for (int t = 0; t < 8; t++) {
            const int jw = warp_n * 32 + t * 4 + tg;
            float e0 = __expf(acc[mt][t][0] * SCALE_);
            float e1 = __expf(acc[mt][t][1] * SCALE_);
            float e2 = __expf(acc[mt][t][2] * SCALE_);
            float e3 = __expf(acc[mt][t][3] * SCALE_);
            rs[mt][0] += e0 + e1;
            rs[mt][1] += e2 + e3;
            pstg[il * EN_STG_STRIDE + jw]       = pack2f(e0, e1);
            pstg[(il + 8) * EN_STG_STRIDE + jw] = pack2f(e2, e3);
        }
    }
#pragma unroll
    for (int mt = 0; mt < 2; mt++)
#pragma unroll
        for (int h = 0; h < 2; h++) {
            float s = rs[mt][h];
            s += __shfl_xor_sync(0xFFFFFFFF, s, 1);
            s += __shfl_xor_sync(0xFFFFFFFF, s, 2);
            if (tg == 0)
                ps[warp_n * 128 + warp_m * 32 + mt * 16 + h * 8 + gp] = s;
        }
    __syncthreads();

    if (tid < 128)
        g_psum[((size_t)b * 16 + jt) * N_ + i0 + tid] =
            ps[tid] + ps[128 + tid] + ps[256 + tid] + ps[384 + tid];

#pragma unroll
    for (int r = 0; r < 8; r++) {
        const int row = wid * 8 + r;
        uint4 v = *(uint4*)(pstg + row * EN_STG_STRIDE + lane * 4);
        *(uint4*)(g_p + ((size_t)b * N_ + i0 + row) * N_ + j0 + lane * 8) = v;
    }
}

// ---------------------------------------------------------------------------
__global__ __launch_bounds__(256) void rowsum_reduce_kernel()
{
    const int r = blockIdx.x * 256 + threadIdx.x;
    const int b = r >> 12, i = r & (N_ - 1);
    float s = 0.f;
#pragma unroll
    for (int jt = 0; jt < 16; jt++)
        s += g_psum[((size_t)b * 16 + jt) * N_ + i];
    g_inv[r] = 1.f / s;
}

// ---------------------------------------------------------------------------
// Output GEMM (512 thr): cp.async.bulk loads (384 x 128B per chunk) + mbarrier.
// CTA 128c x 256i, KC=64, 4 stages.
// ---------------------------------------------------------------------------
#define OUT_ROW 144
#define OUT_A 0
#define OUT_B (128 * OUT_ROW)                      // 18432
#define OUT_STAGE (128 * OUT_ROW + 256 * OUT_ROW)  // 55296
#define OUT_INV (4 * OUT_STAGE)                    // 221184
#define OUT_MBAR (OUT_INV + 1024)                  // 4 x 8B barriers
#define OUT_SMEM (OUT_INV + 1024 + 1024)           // 223232
#define OST 260
#define OUT_TX_BYTES 49152u                        // 384 rows x 128B

__device__ __forceinline__ void out_load_bulk(
    uint32_t sbase, uint32_t mbar, int b, int c0, int i0, int j0, int tid)
{
    if (tid == 0)
        MBARRIER_EXPECT_TX(mbar, OUT_TX_BYTES);
    if (tid < 128) {
#pragma unroll
        for (int k = 0; k < 3; k++) {
            int r = tid + k * 128;          // 0..383
            if (r < 128) {
                bulk128(sbase + OUT_A + r * OUT_ROW,
                        g_v + ((size_t)(b * C_ + c0 + r)) * N_ + j0, mbar);
            } else {
                int rr = r - 128;
                bulk128(sbase + OUT_B + rr * OUT_ROW,
                        g_p + ((size_t)b * N_ + i0 + rr) * N_ + j0, mbar);
            }
        }
    }
}

__global__ __launch_bounds__(512, 1) void out_mma_kernel(
    const float* __restrict__ xs, const float* __restrict__ xt,
    float* __restrict__ out)
{
    extern __shared__ char dsm[];
    uint32_t raw  = smem_u32(dsm);
    uint32_t base = (raw + 1023) & ~1023u;
    char* cbase = dsm + (base - raw);
    float* inv_s = (float*)(cbase + OUT_INV);
    float* stg   = (float*)(cbase);      // epilogue staging (reuses stage 0)
    const uint32_t mb0 = base + OUT_MBAR;

    const int tid = threadIdx.x;
    const int lane = tid & 31;
    const int wid = tid >> 5;
    const int warp_m = wid & 3;      // c: 32 rows
    const int warp_n = wid >> 2;     // i: 64 cols

    const int b  = blockIdx.z;
    const int c0 = blockIdx.x * 128;
    const int i0 = blockIdx.y * 256;

    float acc[2][8][4];
#pragma unroll
    for (int mt = 0; mt < 2; mt++)
#pragma unroll
        for (int t = 0; t < 8; t++)
#pragma unroll
            for (int q = 0; q < 4; q++) acc[mt][t][q] = 0.f;

    if (tid == 0) {
        MBARRIER_INIT(mb0,      1);
        MBARRIER_INIT(mb0 + 8,  1);
        MBARRIER_INIT(mb0 + 16, 1);
        MBARRIER_INIT(mb0 + 24, 1);
    }
    __syncthreads();

    out_load_bulk(base,                 mb0,      b, c0, i0, 0,   tid);
    out_load_bulk(base + OUT_STAGE,     mb0 + 8,  b, c0, i0, 64,  tid);
    out_load_bulk(base + 2 * OUT_STAGE, mb0 + 16, b, c0, i0, 128, tid);

    const int lrow = lane & 15;
    const int lkh  = (lane >> 4) * 16;

    for (int chk = 0; chk < 64; chk++) {
        const int st = chk & 3;
        const uint32_t sb = base + st * OUT_STAGE;
        MBARRIER_WAIT_PARITY(mb0 + st * 8, (chk >> 2) & 1);
        __syncthreads();
        if (chk + 3 < 64)
            out_load_bulk(base + ((chk + 3) & 3) * OUT_STAGE, mb0 + ((chk + 3) & 3) * 8,
                          b, c0, i0, (chk + 3) * 64, tid);

        const uint32_t a_base = sb + OUT_A + (warp_m * 32 + lrow) * OUT_ROW + lkh;
        const uint32_t b_base = sb + OUT_B + (warp_n * 64 + lrow) * OUT_ROW + lkh;

#pragma unroll
        for (int ks = 0; ks < 4; ks++) {
            const uint32_t koff = ks * 32;
            uint32_t ah[2][4];
#pragma unroll
            for (int mt = 0; mt < 2; mt++)
                ldm_x4(ah[mt], a_base + mt * (16 * OUT_ROW) + koff);
#pragma unroll
            for (int ng = 0; ng < 4; ng++) {
                uint32_t bh[4];
                ldm_x4(bh, b_base + ng * (16 * OUT_ROW) + koff);
#pragma unroll
                for (int mt = 0; mt < 2; mt++) {
                    mma16816(acc[mt][ng*2],   ah[mt], bh[0], bh[2]);
                    mma16816(acc[mt][ng*2+1], ah[mt], bh[1], bh[3]);
                }
            }
        }
    }

    if (tid < 256) inv_s[tid] = g_inv[b * N_ + i0 + tid];
    __syncthreads();

    // epilogue: 4 slabs of 32 c-rows, staged fp32 transpose, coalesced stores
    const int gp = lane >> 2, tg = lane & 3;
#pragma unroll 1
    for (int s = 0; s < 4; s++) {
        if (warp_m == s) {
#pragma unroll
            for (int mt = 0; mt < 2; mt++) {
                const int cl = mt * 16 + gp;
#pragma unroll
                for (int t = 0; t < 8; t++) {
                    const int iloc = warp_n * 64 + t * 8 + tg * 2;
                    stg[cl * OST + iloc]           = acc[mt][t][0] * inv_s[iloc];
                    stg[cl * OST + iloc + 1]       = acc[mt][t][1] * inv_s[iloc + 1];
                    stg[(cl + 8) * OST + iloc]     = acc[mt][t][2] * inv_s[iloc];
                    stg[(cl + 8) * OST + iloc + 1] = acc[mt][t][3] * inv_s[iloc + 1];
                }
            }
        }
        __syncthreads();
#pragma unroll
        for (int r = 0; r < 2; r++) {
            const int row = wid * 2 + r;
            const size_t gbase = ((size_t)(b * C_ + c0 + s * 32 + row)) * N_ + i0;
#pragma unroll
            for (int it = 0; it < 2; it++) {
                const int f = (it * 32 + lane) * 4;
                float4 o4 = *(float4*)(stg + row * OST + f);
                float4 x1 = *(const float4*)(xs + gbase + f);
                float4 x2 = *(const float4*)(xt + gbase + f);
                o4.x += x1.x + x2.x;
                o4.y += x1.y + x2.y;
                o4.z += x1.z + x2.z;
                o4.w += x1.w + x2.w;
                *(float4*)(out + gbase + f) = o4;
            }
        }
        __syncthreads();
    }
}

// ---------------------------------------------------------------------------
extern "C" void kernel_launch(void* const* d_in, const int* in_sizes, int n_in,
                              void* d_out, int out_size)
{
    const float* xs  = (const float*)d_in[0];
    const float* xt  = (const float*)d_in[1];
    const float* Wq  = (const float*)d_in[2];
    const float* bq  = (const float*)d_in[3];
    const float* Wk  = (const float*)d_in[4];
    const float* bk  = (const float*)d_in[5];
    const float* Wvs = (const float*)d_in[6];
    const float* bvs = (const float*)d_in[7];
    const float* Wvt = (const float*)d_in[8];
    const float* bvt = (const float*)d_in[9];
    float* out = (float*)d_out;

    static cudaStream_t s2 = nullptr;
    static cudaEvent_t ev_fork = nullptr, ev_join = nullptr;
    if (!s2) {
        cudaFuncSetAttribute(v_proj_mma_kernel, cudaFuncAttributeMaxDynamicSharedMemorySize, VP_SMEM);
        cudaFuncSetAttribute(energy_exp_kernel, cudaFuncAttributeMaxDynamicSharedMemorySize, EN_SMEM);
        cudaFuncSetAttribute(out_mma_kernel,   cudaFuncAttributeMaxDynamicSharedMemorySize, OUT_SMEM);
        cudaStreamCreateWithFlags(&s2, cudaStreamNonBlocking);
        cudaEventCreateWithFlags(&ev_fork, cudaEventDisableTiming);
        cudaEventCreateWithFlags(&ev_join, cudaEventDisableTiming);
    }

    w_cvt_kernel<<<dim3(C_ * C_ / 1024, 2), 256>>>(Wvs, Wvt);
    qk_proj_kernel<<<dim3(N_ / 128, B_, 2), 256>>>(Wq, bq, Wk, bk, xs, xt);

    cudaEventRecord(ev_fork, 0);
    cudaStreamWaitEvent(s2, ev_fork, 0);
    energy_exp_kernel<<<dim3(N_ / 256, N_ / 128, B_), 512, EN_SMEM, s2>>>();
    rowsum_reduce_kernel<<<B_ * N_ / 256, 256, 0, s2>>>();
    v_proj_mma_kernel<<<dim3(N_ / 256, C_ / 128, B_), 512, VP_SMEM>>>(bvs, bvt);

    cudaEventRecord(ev_join, s2);
    cudaStreamWaitEvent(0, ev_join, 0);
    out_mma_kernel<<<dim3(C_ / 128, N_ / 256, B_), 512, OUT_SMEM>>>(xs, xt, out);
}

// round 15
// speedup vs baseline: 1.4143x; 1.4143x over previous
#include <cuda_runtime.h>
#include <cuda_bf16.h>
#include <cstdint>
#include <cstddef>

#define B_   4
#define C_   512
#define N_   4096
#define CQ_  64
#define SCALE_ 0.125f   // (C/8)^-0.5

// ---------------- device scratch (single bf16) ----------
__device__ __nv_bfloat16 g_q[B_ * CQ_ * N_];                  // [b][q][n]
__device__ __nv_bfloat16 g_k[B_ * CQ_ * N_];
__device__ __nv_bfloat16 g_v[(size_t)B_ * C_ * N_];           // [b][c][n]
__device__ __nv_bfloat16 g_p[(size_t)B_ * N_ * N_];           // exp(E) [b][i][j]
__device__ __nv_bfloat16 g_xs[(size_t)B_ * C_ * N_];          // x bf16
__device__ __nv_bfloat16 g_xt[(size_t)B_ * C_ * N_];
__device__ __nv_bfloat16 g_ws[C_ * C_], g_wt[C_ * C_];        // Wvs/Wvt bf16 [c][k]
__device__ float g_psum[B_ * 16 * N_];                        // [b][jt][i]
__device__ float g_inv[B_ * N_];

#define LD8(dst, ptr)                                              \
    do {                                                           \
        float4 _u0 = *(const float4*)((ptr));                      \
        float4 _u1 = *(const float4*)((ptr) + 4);                  \
        (dst)[0]=_u0.x; (dst)[1]=_u0.y; (dst)[2]=_u0.z; (dst)[3]=_u0.w; \
        (dst)[4]=_u1.x; (dst)[5]=_u1.y; (dst)[6]=_u1.z; (dst)[7]=_u1.w; \
    } while (0)

// ====================== helpers ======================
__device__ __forceinline__ uint32_t smem_u32(const void* p) {
    uint32_t a;
    asm("{ .reg .u64 t; cvta.to.shared.u64 t, %1; cvt.u32.u64 %0, t; }" : "=r"(a) : "l"(p));
    return a;
}
__device__ __forceinline__ void cp16(uint32_t dst, const void* src) {
    asm volatile("cp.async.cg.shared.global [%0], [%1], 16;" :: "r"(dst), "l"(src));
}
#define CP_COMMIT() asm volatile("cp.async.commit_group;" ::: "memory")
#define CP_WAIT(n)  asm volatile("cp.async.wait_group %0;" :: "n"(n) : "memory")
__device__ __forceinline__ void ldm_x4(uint32_t* r, uint32_t addr) {
    asm volatile("ldmatrix.sync.aligned.m8n8.x4.shared.b16 {%0,%1,%2,%3}, [%4];"
        : "=r"(r[0]), "=r"(r[1]), "=r"(r[2]), "=r"(r[3]) : "r"(addr));
}
__device__ __forceinline__ void ldm_x4t(uint32_t* r, uint32_t addr) {
    asm volatile("ldmatrix.sync.aligned.m8n8.x4.trans.shared.b16 {%0,%1,%2,%3}, [%4];"
        : "=r"(r[0]), "=r"(r[1]), "=r"(r[2]), "=r"(r[3]) : "r"(addr));
}
__device__ __forceinline__ void mma16816(float* c, const uint32_t* a, uint32_t b0, uint32_t b1) {
    asm volatile(
        "mma.sync.aligned.m16n8k16.row.col.f32.bf16.bf16.f32 "
        "{%0,%1,%2,%3}, {%4,%5,%6,%7}, {%8,%9}, {%0,%1,%2,%3};"
        : "+f"(c[0]), "+f"(c[1]), "+f"(c[2]), "+f"(c[3])
        : "r"(a[0]), "r"(a[1]), "r"(a[2]), "r"(a[3]), "r"(b0), "r"(b1));
}
__device__ __forceinline__ uint32_t pack2f(float a, float b) {
    __nv_bfloat162 t; t.x = __float2bfloat16(a); t.y = __float2bfloat16(b);
    return *(uint32_t*)&t;
}

// ---------------------------------------------------------------------------
// W convert: fp32 -> bf16
// ---------------------------------------------------------------------------
__global__ __launch_bounds__(256) void w_cvt_kernel(
    const float* __restrict__ Wvs, const float* __restrict__ Wvt)
{
    const size_t idx4 = ((size_t)blockIdx.x * 256 + threadIdx.x) * 4;
    const float* src = blockIdx.y ? Wvt : Wvs;
    __nv_bfloat16* dst = blockIdx.y ? g_wt : g_ws;
    float4 v = *(const float4*)(src + idx4);
    uint32_t* p = (uint32_t*)(dst + idx4);
    p[0] = pack2f(v.x, v.y);
    p[1] = pack2f(v.z, v.w);
}

// ---------------------------------------------------------------------------
// Q/K projection fp32 -> bf16 out + x bf16 convert (from smem tile).
// ---------------------------------------------------------------------------
__global__ __launch_bounds__(256, 2) void qk_proj_kernel(
    const float* __restrict__ Wq, const float* __restrict__ bq,
    const float* __restrict__ Wk, const float* __restrict__ bk,
    const float* __restrict__ xs, const float* __restrict__ xt)
{
    __shared__ float Ws[32][68];
    __shared__ float Xs[32][128];

    const int which = blockIdx.z;
    const int b  = blockIdx.y;
    const int n0 = blockIdx.x * 128;
    const float* W = which ? Wk : Wq;
    const float* bias = which ? bk : bq;
    const float* Xb = (which ? xt : xs) + (size_t)b * C_ * N_;
    __nv_bfloat16* Y = which ? g_k : g_q;
    __nv_bfloat16* Xdst = (which ? g_xt : g_xs) + (size_t)b * C_ * N_;

    const int tid = threadIdx.x;
    const int tx = tid & 15;
    const int ty = tid >> 4;

    float acc[4][8];
#pragma unroll
    for (int i = 0; i < 4; i++)
#pragma unroll
        for (int j = 0; j < 8; j++) acc[i][j] = 0.f;

    for (int k0 = 0; k0 < C_; k0 += 32) {
#pragma unroll
        for (int r = 0; r < 8; r++) {
            int idx = tid + r * 256;
            int m = idx >> 5, kk = idx & 31;
            Ws[kk][m] = W[(size_t)m * C_ + k0 + kk];
        }
#pragma unroll
        for (int r = 0; r < 16; r++) {
            int idx = tid + r * 256;
            int kk = idx >> 7, n = idx & 127;
            Xs[kk][n] = Xb[(size_t)(k0 + kk) * N_ + n0 + n];
        }
        __syncthreads();

        // fold-in: emit bf16 copy of this x tile
#pragma unroll
        for (int r = 0; r < 8; r++) {
            int idx = tid + r * 256;            // 32 rows x 64 pairs
            int kk = idx >> 6, np = idx & 63;
            *(uint32_t*)(Xdst + (size_t)(k0 + kk) * N_ + n0 + np * 2) =
                pack2f(Xs[kk][np * 2], Xs[kk][np * 2 + 1]);
        }

#pragma unroll
        for (int kk = 0; kk < 32; kk++) {
            float a[4], bb[8];
#pragma unroll
            for (int i = 0; i < 4; i++) a[i] = Ws[kk][ty * 4 + i];
            LD8(bb, &Xs[kk][tx * 8]);
#pragma unroll
            for (int i = 0; i < 4; i++)
#pragma unroll
                for (int j = 0; j < 8; j++) acc[i][j] += a[i] * bb[j];
        }
        __syncthreads();
    }
#pragma unroll
    for (int i = 0; i < 4; i++) {
        int m = ty * 4 + i;
        float bv = bias[m];
        uint32_t* yp = (uint32_t*)(Y + ((size_t)b * CQ_ + m) * N_ + n0 + tx * 8);
#pragma unroll
        for (int p = 0; p < 4; p++)
            yp[p] = pack2f(acc[i][2*p] + bv, acc[i][2*p+1] + bv);
    }
}

// ---------------------------------------------------------------------------
// V projection (512 thr): V = Wvs@xs + Wvt@xt + bias -> bf16
// CTA 128c x 256n, KC=32, 4 stages (3 in flight, hoisted loads, 1 barrier/chunk)
// ---------------------------------------------------------------------------
#define VP_AROW 80
#define VP_BROW 528
#define VP_AMAT (128 * VP_AROW)
#define VP_BMAT (32 * VP_BROW)
#define VP_WS 0
#define VP_WT VP_AMAT
#define VP_XS (2 * VP_AMAT)
#define VP_XT (2 * VP_AMAT + VP_BMAT)
#define VP_STAGE (2 * VP_AMAT + 2 * VP_BMAT)   // 54272
#define VP_SMEM (4 * VP_STAGE + 1024)          // 218112

__device__ __forceinline__ void vp_load_stage(uint32_t sb, int b, int c0, int n0, int k0, int tid)
{
#pragma unroll
    for (int k = 0; k < 2; k++) {
        int idx = tid + k * 512;
        int mat = idx >> 9, rem = idx & 511;
        int r = rem >> 2, ch = rem & 3;
        const __nv_bfloat16* src = mat ? g_wt : g_ws;
        cp16(sb + mat * VP_AMAT + r * VP_AROW + ch * 16,
             src + (size_t)(c0 + r) * C_ + k0 + ch * 8);
    }
#pragma unroll
    for (int k = 0; k < 4; k++) {
        int idx = tid + k * 512;
        int mat = idx >> 10, rem = idx & 1023;
        int r = rem >> 5, ch = rem & 31;
        const __nv_bfloat16* src = mat ? g_xt : g_xs;
        cp16(sb + 2 * VP_AMAT + mat * VP_BMAT + r * VP_BROW + ch * 16,
             src + ((size_t)b * C_ + k0 + r) * N_ + n0 + ch * 8);
    }
    CP_COMMIT();
}

__global__ __launch_bounds__(512, 1) void v_proj_mma_kernel(
    const float* __restrict__ bvs, const float* __restrict__ bvt)
{
    extern __shared__ char dsm[];
    uint32_t raw  = smem_u32(dsm);
    uint32_t base = (raw + 1023) & ~1023u;

    const int tid = threadIdx.x;
    const int lane = tid & 31;
    const int wid = tid >> 5;
    const int warp_m = wid & 3;
    const int warp_n = wid >> 2;

    const int b  = blockIdx.z;
    const int c0 = blockIdx.y * 128;
    const int n0 = blockIdx.x * 256;

    float acc[2][8][4];
#pragma unroll
    for (int mt = 0; mt < 2; mt++)
#pragma unroll
        for (int t = 0; t < 8; t++)
#pragma unroll
            for (int q = 0; q < 4; q++) acc[mt][t][q] = 0.f;

    vp_load_stage(base,                b, c0, n0, 0,  tid);
    vp_load_stage(base + VP_STAGE,     b, c0, n0, 32, tid);
    vp_load_stage(base + 2 * VP_STAGE, b, c0, n0, 64, tid);

    const uint32_t a_lrow = (uint32_t)(warp_m * 32 + (lane & 15));
    const uint32_t a_lcol = (uint32_t)((lane >> 4) * 16);
    const uint32_t b_lrow = (uint32_t)((lane & 7) | (lane & 8));
    const uint32_t b_lcol = (uint32_t)((warp_n * 64 + ((lane >> 4) & 1) * 8) * 2);

    for (int chk = 0; chk < 16; chk++) {
        const uint32_t sb = base + (chk & 3) * VP_STAGE;
        if (chk <= 13)      CP_WAIT(2);
        else if (chk == 14) CP_WAIT(1);
        else                CP_WAIT(0);
        __syncthreads();
        if (chk + 3 < 16)
            vp_load_stage(base + ((chk + 3) & 3) * VP_STAGE, b, c0, n0, (chk + 3) * 32, tid);

#pragma unroll
        for (int ks = 0; ks < 2; ks++) {
            uint32_t ws[2][4], wt[2][4];
#pragma unroll
            for (int mt = 0; mt < 2; mt++) {
                uint32_t aoff = (a_lrow + mt * 16) * VP_AROW + a_lcol + ks * 32;
                ldm_x4(ws[mt], sb + VP_WS + aoff);
                ldm_x4(wt[mt], sb + VP_WT + aoff);
            }
#pragma unroll
            for (int ng = 0; ng < 4; ng++) {
                uint32_t boff = (b_lrow + ks * 16) * VP_BROW + b_lcol + ng * 32;
                uint32_t xsf[4], xtf[4];
                ldm_x4t(xsf, sb + VP_XS + boff);
                ldm_x4t(xtf, sb + VP_XT + boff);
#pragma unroll
                for (int mt = 0; mt < 2; mt++)
#pragma unroll
                    for (int sub = 0; sub < 2; sub++) {
                        float* a = acc[mt][ng * 2 + sub];
                        uint32_t s0 = sub ? xsf[2] : xsf[0], s1 = sub ? xsf[3] : xsf[1];
                        uint32_t t0 = sub ? xtf[2] : xtf[0], t1 = sub ? xtf[3] : xtf[1];
                        mma16816(a, ws[mt], s0, s1);
                        mma16816(a, wt[mt], t0, t1);
                    }
            }
        }
    }

    const int gp = lane >> 2, tg = lane & 3;
#pragma unroll
    for (int mt = 0; mt < 2; mt++) {
        const int r0 = c0 + warp_m * 32 + mt * 16 + gp;
        const float bv0 = bvs[r0] + bvt[r0];
        const float bv1 = bvs[r0 + 8] + bvt[r0 + 8];
#pragma unroll
        for (int t = 0; t < 8; t++) {
            const int nc = n0 + warp_n * 64 + t * 8 + tg * 2;
            size_t i0 = ((size_t)b * C_ + r0) * N_ + nc;
            size_t i1 = i0 + 8 * (size_t)N_;
            *(uint32_t*)(g_v + i0) = pack2f(acc[mt][t][0] + bv0, acc[mt][t][1] + bv0);
            *(uint32_t*)(g_v + i1) = pack2f(acc[mt][t][2] + bv1, acc[mt][t][3] + bv1);
        }
    }
}

// ---------------------------------------------------------------------------
// Energy + exp (512 thr): P = exp(SCALE * Q^T K) -> bf16 (smem-staged,
// coalesced STG.128) + partial rowsums. CTA 128i x 256j. 16 warps: 4i x 4j.
// ---------------------------------------------------------------------------
#define EQ_ROW 272
#define EK_ROW 528
#define EN_Q 0
#define EN_QB (CQ_ * EQ_ROW)          // 17408
#define EN_K EN_QB
#define EN_KB (CQ_ * EK_ROW)          // 33792
#define EN_STG (EN_QB + EN_KB)        // 51200
#define EN_STG_STRIDE 132             // uint32 words per row (16B-aligned)
#define EN_STG_BYTES (128 * EN_STG_STRIDE * 4)   // 67584
#define EN_PS (EN_STG + EN_STG_BYTES)
#define EN_SMEM (EN_PS + 2048 + 1024)

__global__ __launch_bounds__(512, 1) void energy_exp_kernel()
{
    extern __shared__ char dsm[];
    uint32_t raw  = smem_u32(dsm);
    uint32_t base = (raw + 1023) & ~1023u;
    char* cbase = dsm + (base - raw);
    float* ps = (float*)(cbase + EN_PS);
    uint32_t* pstg = (uint32_t*)(cbase + EN_STG);

    const int tid = threadIdx.x;
    const int lane = tid & 31;
    const int wid = tid >> 5;
    const int warp_m = wid & 3;      // i
    const int warp_n = wid >> 2;     // j

    const int b  = blockIdx.z;
    const int i0 = blockIdx.y * 128;
    const int jt = blockIdx.x;
    const int j0 = jt * 256;

#pragma unroll
    for (int k = 0; k < 2; k++) {                  // Q: 64 rows x 16 chunks
        int idx = tid + k * 512;
        int r = idx >> 4, ch = idx & 15;
        cp16(base + EN_Q + r * EQ_ROW + ch * 16,
             g_q + ((size_t)b * CQ_ + r) * N_ + i0 + ch * 8);
    }
#pragma unroll
    for (int k = 0; k < 4; k++) {                  // K: 64 rows x 32 chunks
        int idx = tid + k * 512;
        int r = idx >> 5, ch = idx & 31;
        cp16(base + EN_K + r * EK_ROW + ch * 16,
             g_k + ((size_t)b * CQ_ + r) * N_ + j0 + ch * 8);
    }
    CP_COMMIT();
    CP_WAIT(0);
    __syncthreads();

    float acc[2][8][4];
#pragma unroll
    for (int mt = 0; mt < 2; mt++)
#pragma unroll
        for (int t = 0; t < 8; t++)
#pragma unroll
            for (int q = 0; q < 4; q++) acc[mt][t][q] = 0.f;

    const uint32_t aq_row = (uint32_t)((lane & 7) | ((lane >> 4) << 3));
    const uint32_t aq_col = (uint32_t)((warp_m * 32 + ((lane >> 3) & 1) * 8) * 2);
    const uint32_t bk_row = (uint32_t)((lane & 7) | (lane & 8));
    const uint32_t bk_col = (uint32_t)((warp_n * 64 + ((lane >> 4) & 1) * 8) * 2);

#pragma unroll
    for (int ks = 0; ks < 4; ks++) {
        uint32_t ah[2][4];
#pragma unroll
        for (int mt = 0; mt < 2; mt++) {
            uint32_t aoff = (aq_row + ks * 16) * EQ_ROW + aq_col + mt * 32;
            ldm_x4t(ah[mt], base + EN_Q + aoff);
        }
#pragma unroll
        for (int ng = 0; ng < 4; ng++) {
            uint32_t boff = (bk_row + ks * 16) * EK_ROW + bk_col + ng * 32;
            uint32_t bh[4];
            ldm_x4t(bh, base + EN_K + boff);
#pragma unroll
            for (int mt = 0; mt < 2; mt++)
#pragma unroll
                for (int sub = 0; sub < 2; sub++) {
                    float* a = acc[mt][ng * 2 + sub];
                    uint32_t p0 = sub ? bh[2] : bh[0], p1 = sub ? bh[3] : bh[1];
                    mma16816(a, ah[mt], p0, p1);
                }
        }
    }

    // epilogue: exp -> smem staging, rowsums in regs
    const int gp = lane >> 2, tg = lane & 3;
    float rs[2][2] = {{0.f, 0.f}, {0.f, 0.f}};
#pragma unroll
    for (int mt = 0; mt < 2; mt++) {
        const int il = warp_m * 32 + mt * 16 + gp;
#pragma unroll
        for (int t = 0; t < 8; t++) {
            const int jw = warp_n * 32 + t * 4 + tg;
            float e0 = __expf(acc[mt][t][0] * SCALE_);
            float e1 = __expf(acc[mt][t][1] * SCALE_);
            float e2 = __expf(acc[mt][t][2] * SCALE_);
            float e3 = __expf(acc[mt][t][3] * SCALE_);
            rs[mt][0] += e0 + e1;
            rs[mt][1] += e2 + e3;
            pstg[il * EN_STG_STRIDE + jw]       = pack2f(e0, e1);
            pstg[(il + 8) * EN_STG_STRIDE + jw] = pack2f(e2, e3);
        }
    }
#pragma unroll
    for (int mt = 0; mt < 2; mt++)
#pragma unroll
        for (int h = 0; h < 2; h++) {
            float s = rs[mt][h];
            s += __shfl_xor_sync(0xFFFFFFFF, s, 1);
            s += __shfl_xor_sync(0xFFFFFFFF, s, 2);
            if (tg == 0)
                ps[warp_n * 128 + warp_m * 32 + mt * 16 + h * 8 + gp] = s;
        }
    __syncthreads();

    if (tid < 128)
        g_psum[((size_t)b * 16 + jt) * N_ + i0 + tid] =
            ps[tid] + ps[128 + tid] + ps[256 + tid] + ps[384 + tid];

    // coalesced store: warp wid handles rows wid*8 .. wid*8+7
#pragma unroll
    for (int r = 0; r < 8; r++) {
        const int row = wid * 8 + r;
        uint4 v = *(uint4*)(pstg + row * EN_STG_STRIDE + lane * 4);
        *(uint4*)(g_p + ((size_t)b * N_ + i0 + row) * N_ + j0 + lane * 8) = v;
    }
}

// ---------------------------------------------------------------------------
__global__ __launch_bounds__(256) void rowsum_reduce_kernel()
{
    const int r = blockIdx.x * 256 + threadIdx.x;
    const int b = r >> 12, i = r & (N_ - 1);
    float s = 0.f;
#pragma unroll
    for (int jt = 0; jt < 16; jt++)
        s += g_psum[((size_t)b * 16 + jt) * N_ + i];
    g_inv[r] = 1.f / s;
}

// ---------------------------------------------------------------------------
// Output GEMM (512 thr): D[c][i] = sum_j V[c][j] P[i][j]; out = D*inv + xs + xt
// CTA 128c x 256i, KC=64, 4 stages (3 in flight, hoisted loads, 1 barrier/chunk)
// ---------------------------------------------------------------------------
#define OUT_ROW 144
#define OUT_A 0
#define OUT_B (128 * OUT_ROW)                      // 18432
#define OUT_STAGE (128 * OUT_ROW + 256 * OUT_ROW)  // 55296
#define OUT_INV (4 * OUT_STAGE)                    // 221184
#define OUT_SMEM (4 * OUT_STAGE + 1024 + 1024)     // 223232
#define OST 260                                    // epilogue fp32 row stride (1040B)

__device__ __forceinline__ void out_load_stage(uint32_t sb, int b, int c0, int i0, int j0, int tid)
{
#pragma unroll
    for (int k = 0; k < 2; k++) {          // A: 128 rows x 8 chunks
        int idx = tid + k * 512;
        int row = idx >> 3, ch = idx & 7;
        cp16(sb + OUT_A + row * OUT_ROW + ch * 16,
             g_v + ((size_t)(b * C_ + c0 + row)) * N_ + j0 + ch * 8);
    }
#pragma unroll
    for (int k = 0; k < 4; k++) {          // B: 256 rows x 8 chunks
        int idx = tid + k * 512;
        int row = idx >> 3, ch = idx & 7;
        cp16(sb + OUT_B + row * OUT_ROW + ch * 16,
             g_p + ((size_t)b * N_ + i0 + row) * N_ + j0 + ch * 8);
    }
    CP_COMMIT();
}

__global__ __launch_bounds__(512, 1) void out_mma_kernel(
    const float* __restrict__ xs, const float* __restrict__ xt,
    float* __restrict__ out)
{
    extern __shared__ char dsm[];
    uint32_t raw  = smem_u32(dsm);
    uint32_t base = (raw + 1023) & ~1023u;
    char* cbase = dsm + (base - raw);
    float* inv_s = (float*)(cbase + OUT_INV);
    float* stg   = (float*)(cbase);      // epilogue staging (reuses stage 0)

    const int tid = threadIdx.x;
    const int lane = tid & 31;
    const int wid = tid >> 5;
    const int warp_m = wid & 3;      // c: 32 rows
    const int warp_n = wid >> 2;     // i: 64 cols

    const int b  = blockIdx.z;
    const int c0 = blockIdx.x * 128;
    const int i0 = blockIdx.y * 256;

    float acc[2][8][4];
#pragma unroll
    for (int mt = 0; mt < 2; mt++)
#pragma unroll
        for (int t = 0; t < 8; t++)
#pragma unroll
            for (int q = 0; q < 4; q++) acc[mt][t][q] = 0.f;

    out_load_stage(base,                 b, c0, i0, 0,   tid);
    out_load_stage(base + OUT_STAGE,     b, c0, i0, 64,  tid);
    out_load_stage(base + 2 * OUT_STAGE, b, c0, i0, 128, tid);

    const int lrow = lane & 15;
    const int lkh  = (lane >> 4) * 16;

    for (int chk = 0; chk < 64; chk++) {
        const uint32_t sb = base + (chk & 3) * OUT_STAGE;
        if (chk <= 61)      CP_WAIT(2);
        else if (chk == 62) CP_WAIT(1);
        else                CP_WAIT(0);
        __syncthreads();
        if (chk + 3 < 64)
            out_load_stage(base + ((chk + 3) & 3) * OUT_STAGE, b, c0, i0, (chk + 3) * 64, tid);

        const uint32_t a_base = sb + OUT_A + (warp_m * 32 + lrow) * OUT_ROW + lkh;
        const uint32_t b_base = sb + OUT_B + (warp_n * 64 + lrow) * OUT_ROW + lkh;

#pragma unroll
        for (int ks = 0; ks < 4; ks++) {
            const uint32_t koff = ks * 32;
            uint32_t ah[2][4];
#pragma unroll
            for (int mt = 0; mt < 2; mt++)
                ldm_x4(ah[mt], a_base + mt * (16 * OUT_ROW) + koff);
#pragma unroll
            for (int ng = 0; ng < 4; ng++) {
                uint32_t bh[4];
                ldm_x4(bh, b_base + ng * (16 * OUT_ROW) + koff);
#pragma unroll
                for (int mt = 0; mt < 2; mt++) {
                    mma16816(acc[mt][ng*2],   ah[mt], bh[0], bh[2]);
                    mma16816(acc[mt][ng*2+1], ah[mt], bh[1], bh[3]);
                }
            }
        }
    }

    if (tid < 256) inv_s[tid] = g_inv[b * N_ + i0 + tid];
    __syncthreads();

    // epilogue: 4 slabs of 32 c-rows, staged fp32 transpose, coalesced stores
    const int gp = lane >> 2, tg = lane & 3;
#pragma unroll 1
    for (int s = 0; s < 4; s++) {
        if (warp_m == s) {
#pragma unroll
            for (int mt = 0; mt < 2; mt++) {
                const int cl = mt * 16 + gp;
#pragma unroll
                for (int t = 0; t < 8; t++) {
                    const int iloc = warp_n * 64 + t * 8 + tg * 2;
                    stg[cl * OST + iloc]           = acc[mt][t][0] * inv_s[iloc];
                    stg[cl * OST + iloc + 1]       = acc[mt][t][1] * inv_s[iloc + 1];
                    stg[(cl + 8) * OST + iloc]     = acc[mt][t][2] * inv_s[iloc];
                    stg[(cl + 8) * OST + iloc + 1] = acc[mt][t][3] * inv_s[iloc + 1];
                }
            }
        }
        __syncthreads();
#pragma unroll
        for (int r = 0; r < 2; r++) {
            const int row = wid * 2 + r;
            const size_t gbase = ((size_t)(b * C_ + c0 + s * 32 + row)) * N_ + i0;
#pragma unroll
            for (int it = 0; it < 2; it++) {
                const int f = (it * 32 + lane) * 4;
                float4 o4 = *(float4*)(stg + row * OST + f);
                float4 x1 = *(const float4*)(xs + gbase + f);
                float4 x2 = *(const float4*)(xt + gbase + f);
                o4.x += x1.x + x2.x;
                o4.y += x1.y + x2.y;
                o4.z += x1.z + x2.z;
                o4.w += x1.w + x2.w;
                *(float4*)(out + gbase + f) = o4;
            }
        }
        __syncthreads();
    }
}

// ---------------------------------------------------------------------------
extern "C" void kernel_launch(void* const* d_in, const int* in_sizes, int n_in,
                              void* d_out, int out_size)
{
    const float* xs  = (const float*)d_in[0];
    const float* xt  = (const float*)d_in[1];
    const float* Wq  = (const float*)d_in[2];
    const float* bq  = (const float*)d_in[3];
    const float* Wk  = (const float*)d_in[4];
    const float* bk  = (const float*)d_in[5];
    const float* Wvs = (const float*)d_in[6];
    const float* bvs = (const float*)d_in[7];
    const float* Wvt = (const float*)d_in[8];
    const float* bvt = (const float*)d_in[9];
    float* out = (float*)d_out;

    static cudaStream_t s2 = nullptr;
    static cudaEvent_t ev_fork = nullptr, ev_join = nullptr;
    if (!s2) {
        cudaFuncSetAttribute(v_proj_mma_kernel, cudaFuncAttributeMaxDynamicSharedMemorySize, VP_SMEM);
        cudaFuncSetAttribute(energy_exp_kernel, cudaFuncAttributeMaxDynamicSharedMemorySize, EN_SMEM);
        cudaFuncSetAttribute(out_mma_kernel,   cudaFuncAttributeMaxDynamicSharedMemorySize, OUT_SMEM);
        cudaStreamCreateWithFlags(&s2, cudaStreamNonBlocking);
        cudaEventCreateWithFlags(&ev_fork, cudaEventDisableTiming);
        cudaEventCreateWithFlags(&ev_join, cudaEventDisableTiming);
    }

    w_cvt_kernel<<<dim3(C_ * C_ / 1024, 2), 256>>>(Wvs, Wvt);
    qk_proj_kernel<<<dim3(N_ / 128, B_, 2), 256>>>(Wq, bq, Wk, bk, xs, xt);

    // fork: energy+rowsum on s2, v_proj on default stream (independent)
    cudaEventRecord(ev_fork, 0);
    cudaStreamWaitEvent(s2, ev_fork, 0);
    energy_exp_kernel<<<dim3(N_ / 256, N_ / 128, B_), 512, EN_SMEM, s2>>>();
    rowsum_reduce_kernel<<<B_ * N_ / 256, 256, 0, s2>>>();
    v_proj_mma_kernel<<<dim3(N_ / 256, C_ / 128, B_), 512, VP_SMEM>>>(bvs, bvt);

    // join: out needs both V (default stream) and g_inv/g_p (s2)
    cudaEventRecord(ev_join, s2);
    cudaStreamWaitEvent(0, ev_join, 0);
    out_mma_kernel<<<dim3(C_ / 128, N_ / 256, B_), 512, OUT_SMEM>>>(xs, xt, out);
}

// round 16
// speedup vs baseline: 1.4306x; 1.0116x over previous
#include <cuda_runtime.h>
#include <cuda_bf16.h>
#include <cstdint>
#include <cstddef>

#define B_   4
#define C_   512
#define N_   4096
#define CQ_  64
#define SCALE_ 0.125f   // (C/8)^-0.5

// ---------------- device scratch (single bf16) ----------
__device__ __nv_bfloat16 g_q[B_ * CQ_ * N_];                  // [b][q][n]
__device__ __nv_bfloat16 g_k[B_ * CQ_ * N_];
__device__ __nv_bfloat16 g_v[(size_t)B_ * C_ * N_];           // [b][c][n]
__device__ __nv_bfloat16 g_p[(size_t)B_ * N_ * N_];           // exp(E) [b][i][j]
__device__ __nv_bfloat16 g_xs[(size_t)B_ * C_ * N_];          // x bf16
__device__ __nv_bfloat16 g_xt[(size_t)B_ * C_ * N_];
__device__ __nv_bfloat16 g_ws[C_ * C_], g_wt[C_ * C_];        // Wvs/Wvt bf16 [c][k]
__device__ float g_psum[B_ * 16 * N_];                        // [b][jt][i]
__device__ float g_inv[B_ * N_];

#define LD8(dst, ptr)                                              \
    do {                                                           \
        float4 _u0 = *(const float4*)((ptr));                      \
        float4 _u1 = *(const float4*)((ptr) + 4);                  \
        (dst)[0]=_u0.x; (dst)[1]=_u0.y; (dst)[2]=_u0.z; (dst)[3]=_u0.w; \
        (dst)[4]=_u1.x; (dst)[5]=_u1.y; (dst)[6]=_u1.z; (dst)[7]=_u1.w; \
    } while (0)

// ====================== helpers ======================
__device__ __forceinline__ uint32_t smem_u32(const void* p) {
    uint32_t a;
    asm("{ .reg .u64 t; cvta.to.shared.u64 t, %1; cvt.u32.u64 %0, t; }" : "=r"(a) : "l"(p));
    return a;
}
__device__ __forceinline__ void cp16(uint32_t dst, const void* src) {
    asm volatile("cp.async.cg.shared.global [%0], [%1], 16;" :: "r"(dst), "l"(src));
}
#define CP_COMMIT() asm volatile("cp.async.commit_group;" ::: "memory")
#define CP_WAIT(n)  asm volatile("cp.async.wait_group %0;" :: "n"(n) : "memory")
__device__ __forceinline__ void ldm_x4(uint32_t* r, uint32_t addr) {
    asm volatile("ldmatrix.sync.aligned.m8n8.x4.shared.b16 {%0,%1,%2,%3}, [%4];"
        : "=r"(r[0]), "=r"(r[1]), "=r"(r[2]), "=r"(r[3]) : "r"(addr));
}
__device__ __forceinline__ void ldm_x4t(uint32_t* r, uint32_t addr) {
    asm volatile("ldmatrix.sync.aligned.m8n8.x4.trans.shared.b16 {%0,%1,%2,%3}, [%4];"
        : "=r"(r[0]), "=r"(r[1]), "=r"(r[2]), "=r"(r[3]) : "r"(addr));
}
__device__ __forceinline__ void mma16816(float* c, const uint32_t* a, uint32_t b0, uint32_t b1) {
    asm volatile(
        "mma.sync.aligned.m16n8k16.row.col.f32.bf16.bf16.f32 "
        "{%0,%1,%2,%3}, {%4,%5,%6,%7}, {%8,%9}, {%0,%1,%2,%3};"
        : "+f"(c[0]), "+f"(c[1]), "+f"(c[2]), "+f"(c[3])
        : "r"(a[0]), "r"(a[1]), "r"(a[2]), "r"(a[3]), "r"(b0), "r"(b1));
}
__device__ __forceinline__ uint32_t pack2f(float a, float b) {
    __nv_bfloat162 t; t.x = __float2bfloat16(a); t.y = __float2bfloat16(b);
    return *(uint32_t*)&t;
}

// ---------------------------------------------------------------------------
// W convert: fp32 -> bf16
// ---------------------------------------------------------------------------
__global__ __launch_bounds__(256) void w_cvt_kernel(
    const float* __restrict__ Wvs, const float* __restrict__ Wvt)
{
    const size_t idx4 = ((size_t)blockIdx.x * 256 + threadIdx.x) * 4;
    const float* src = blockIdx.y ? Wvt : Wvs;
    __nv_bfloat16* dst = blockIdx.y ? g_wt : g_ws;
    float4 v = *(const float4*)(src + idx4);
    uint32_t* p = (uint32_t*)(dst + idx4);
    p[0] = pack2f(v.x, v.y);
    p[1] = pack2f(v.z, v.w);
}

// ---------------------------------------------------------------------------
// Q/K projection fp32 -> bf16 out + x bf16 convert (from smem tile).
// ---------------------------------------------------------------------------
__global__ __launch_bounds__(256, 2) void qk_proj_kernel(
    const float* __restrict__ Wq, const float* __restrict__ bq,
    const float* __restrict__ Wk, const float* __restrict__ bk,
    const float* __restrict__ xs, const float* __restrict__ xt)
{
    __shared__ float Ws[32][68];
    __shared__ float Xs[32][128];

    const int which = blockIdx.z;
    const int b  = blockIdx.y;
    const int n0 = blockIdx.x * 128;
    const float* W = which ? Wk : Wq;
    const float* bias = which ? bk : bq;
    const float* Xb = (which ? xt : xs) + (size_t)b * C_ * N_;
    __nv_bfloat16* Y = which ? g_k : g_q;
    __nv_bfloat16* Xdst = (which ? g_xt : g_xs) + (size_t)b * C_ * N_;

    const int tid = threadIdx.x;
    const int tx = tid & 15;
    const int ty = tid >> 4;

    float acc[4][8];
#pragma unroll
    for (int i = 0; i < 4; i++)
#pragma unroll
        for (int j = 0; j < 8; j++) acc[i][j] = 0.f;

    for (int k0 = 0; k0 < C_; k0 += 32) {
#pragma unroll
        for (int r = 0; r < 8; r++) {
            int idx = tid + r * 256;
            int m = idx >> 5, kk = idx & 31;
            Ws[kk][m] = W[(size_t)m * C_ + k0 + kk];
        }
#pragma unroll
        for (int r = 0; r < 16; r++) {
            int idx = tid + r * 256;
            int kk = idx >> 7, n = idx & 127;
            Xs[kk][n] = Xb[(size_t)(k0 + kk) * N_ + n0 + n];
        }
        __syncthreads();

        // fold-in: emit bf16 copy of this x tile
#pragma unroll
        for (int r = 0; r < 8; r++) {
            int idx = tid + r * 256;            // 32 rows x 64 pairs
            int kk = idx >> 6, np = idx & 63;
            *(uint32_t*)(Xdst + (size_t)(k0 + kk) * N_ + n0 + np * 2) =
                pack2f(Xs[kk][np * 2], Xs[kk][np * 2 + 1]);
        }

#pragma unroll
        for (int kk = 0; kk < 32; kk++) {
            float a[4], bb[8];
#pragma unroll
            for (int i = 0; i < 4; i++) a[i] = Ws[kk][ty * 4 + i];
            LD8(bb, &Xs[kk][tx * 8]);
#pragma unroll
            for (int i = 0; i < 4; i++)
#pragma unroll
                for (int j = 0; j < 8; j++) acc[i][j] += a[i] * bb[j];
        }
        __syncthreads();
    }
#pragma unroll
    for (int i = 0; i < 4; i++) {
        int m = ty * 4 + i;
        float bv = bias[m];
        uint32_t* yp = (uint32_t*)(Y + ((size_t)b * CQ_ + m) * N_ + n0 + tx * 8);
#pragma unroll
        for (int p = 0; p < 4; p++)
            yp[p] = pack2f(acc[i][2*p] + bv, acc[i][2*p+1] + bv);
    }
}

// ---------------------------------------------------------------------------
// V projection (512 thr): V = Wvs@xs + Wvt@xt + bias -> bf16. b = b0 + z.
// ---------------------------------------------------------------------------
#define VP_AROW 80
#define VP_BROW 528
#define VP_AMAT (128 * VP_AROW)
#define VP_BMAT (32 * VP_BROW)
#define VP_WS 0
#define VP_WT VP_AMAT
#define VP_XS (2 * VP_AMAT)
#define VP_XT (2 * VP_AMAT + VP_BMAT)
#define VP_STAGE (2 * VP_AMAT + 2 * VP_BMAT)   // 54272
#define VP_SMEM (4 * VP_STAGE + 1024)          // 218112

__device__ __forceinline__ void vp_load_stage(uint32_t sb, int b, int c0, int n0, int k0, int tid)
{
#pragma unroll
    for (int k = 0; k < 2; k++) {
        int idx = tid + k * 512;
        int mat = idx >> 9, rem = idx & 511;
        int r = rem >> 2, ch = rem & 3;
        const __nv_bfloat16* src = mat ? g_wt : g_ws;
        cp16(sb + mat * VP_AMAT + r * VP_AROW + ch * 16,
             src + (size_t)(c0 + r) * C_ + k0 + ch * 8);
    }
#pragma unroll
    for (int k = 0; k < 4; k++) {
        int idx = tid + k * 512;
        int mat = idx >> 10, rem = idx & 1023;
        int r = rem >> 5, ch = rem & 31;
        const __nv_bfloat16* src = mat ? g_xt : g_xs;
        cp16(sb + 2 * VP_AMAT + mat * VP_BMAT + r * VP_BROW + ch * 16,
             src + ((size_t)b * C_ + k0 + r) * N_ + n0 + ch * 8);
    }
    CP_COMMIT();
}

__global__ __launch_bounds__(512, 1) void v_proj_mma_kernel(
    const float* __restrict__ bvs, const float* __restrict__ bvt, int b0)
{
    extern __shared__ char dsm[];
    uint32_t raw  = smem_u32(dsm);
    uint32_t base = (raw + 1023) & ~1023u;

    const int tid = threadIdx.x;
    const int lane = tid & 31;
    const int wid = tid >> 5;
    const int warp_m = wid & 3;
    const int warp_n = wid >> 2;

    const int b  = b0 + blockIdx.z;
    const int c0 = blockIdx.y * 128;
    const int n0 = blockIdx.x * 256;

    float acc[2][8][4];
#pragma unroll
    for (int mt = 0; mt < 2; mt++)
#pragma unroll
        for (int t = 0; t < 8; t++)
#pragma unroll
            for (int q = 0; q < 4; q++) acc[mt][t][q] = 0.f;

    vp_load_stage(base,                b, c0, n0, 0,  tid);
    vp_load_stage(base + VP_STAGE,     b, c0, n0, 32, tid);
    vp_load_stage(base + 2 * VP_STAGE, b, c0, n0, 64, tid);

    const uint32_t a_lrow = (uint32_t)(warp_m * 32 + (lane & 15));
    const uint32_t a_lcol = (uint32_t)((lane >> 4) * 16);
    const uint32_t b_lrow = (uint32_t)((lane & 7) | (lane & 8));
    const uint32_t b_lcol = (uint32_t)((warp_n * 64 + ((lane >> 4) & 1) * 8) * 2);

    for (int chk = 0; chk < 16; chk++) {
        const uint32_t sb = base + (chk & 3) * VP_STAGE;
        if (chk <= 13)      CP_WAIT(2);
        else if (chk == 14) CP_WAIT(1);
        else                CP_WAIT(0);
        __syncthreads();
        if (chk + 3 < 16)
            vp_load_stage(base + ((chk + 3) & 3) * VP_STAGE, b, c0, n0, (chk + 3) * 32, tid);

#pragma unroll
        for (int ks = 0; ks < 2; ks++) {
            uint32_t ws[2][4], wt[2][4];
#pragma unroll
            for (int mt = 0; mt < 2; mt++) {
                uint32_t aoff = (a_lrow + mt * 16) * VP_AROW + a_lcol + ks * 32;
                ldm_x4(ws[mt], sb + VP_WS + aoff);
                ldm_x4(wt[mt], sb + VP_WT + aoff);
            }
#pragma unroll
            for (int ng = 0; ng < 4; ng++) {
                uint32_t boff = (b_lrow + ks * 16) * VP_BROW + b_lcol + ng * 32;
                uint32_t xsf[4], xtf[4];
                ldm_x4t(xsf, sb + VP_XS + boff);
                ldm_x4t(xtf, sb + VP_XT + boff);
#pragma unroll
                for (int mt = 0; mt < 2; mt++)
#pragma unroll
                    for (int sub = 0; sub < 2; sub++) {
                        float* a = acc[mt][ng * 2 + sub];
                        uint32_t s0 = sub ? xsf[2] : xsf[0], s1 = sub ? xsf[3] : xsf[1];
                        uint32_t t0 = sub ? xtf[2] : xtf[0], t1 = sub ? xtf[3] : xtf[1];
                        mma16816(a, ws[mt], s0, s1);
                        mma16816(a, wt[mt], t0, t1);
                    }
            }
        }
    }

    const int gp = lane >> 2, tg = lane & 3;
#pragma unroll
    for (int mt = 0; mt < 2; mt++) {
        const int r0 = c0 + warp_m * 32 + mt * 16 + gp;
        const float bv0 = bvs[r0] + bvt[r0];
        const float bv1 = bvs[r0 + 8] + bvt[r0 + 8];
#pragma unroll
        for (int t = 0; t < 8; t++) {
            const int nc = n0 + warp_n * 64 + t * 8 + tg * 2;
            size_t i0 = ((size_t)b * C_ + r0) * N_ + nc;
            size_t i1 = i0 + 8 * (size_t)N_;
            *(uint32_t*)(g_v + i0) = pack2f(acc[mt][t][0] + bv0, acc[mt][t][1] + bv0);
            *(uint32_t*)(g_v + i1) = pack2f(acc[mt][t][2] + bv1, acc[mt][t][3] + bv1);
        }
    }
}

// ---------------------------------------------------------------------------
// Energy + exp (512 thr). b = b0 + z.
// ---------------------------------------------------------------------------
#define EQ_ROW 272
#define EK_ROW 528
#define EN_Q 0
#define EN_QB (CQ_ * EQ_ROW)          // 17408
#define EN_K EN_QB
#define EN_KB (CQ_ * EK_ROW)          // 33792
#define EN_STG (EN_QB + EN_KB)        // 51200
#define EN_STG_STRIDE 132             // uint32 words per row (16B-aligned)
#define EN_STG_BYTES (128 * EN_STG_STRIDE * 4)   // 67584
#define EN_PS (EN_STG + EN_STG_BYTES)
#define EN_SMEM (EN_PS + 2048 + 1024)

__global__ __launch_bounds__(512, 1) void energy_exp_kernel(int b0)
{
    extern __shared__ char dsm[];
    uint32_t raw  = smem_u32(dsm);
    uint32_t base = (raw + 1023) & ~1023u;
    char* cbase = dsm + (base - raw);
    float* ps = (float*)(cbase + EN_PS);
    uint32_t* pstg = (uint32_t*)(cbase + EN_STG);

    const int tid = threadIdx.x;
    const int lane = tid & 31;
    const int wid = tid >> 5;
    const int warp_m = wid & 3;      // i
    const int warp_n = wid >> 2;     // j

    const int b  = b0 + blockIdx.z;
    const int i0 = blockIdx.y * 128;
    const int jt = blockIdx.x;
    const int j0 = jt * 256;

#pragma unroll
    for (int k = 0; k < 2; k++) {                  // Q: 64 rows x 16 chunks
        int idx = tid + k * 512;
        int r = idx >> 4, ch = idx & 15;
        cp16(base + EN_Q + r * EQ_ROW + ch * 16,
             g_q + ((size_t)b * CQ_ + r) * N_ + i0 + ch * 8);
    }
#pragma unroll
    for (int k = 0; k < 4; k++) {                  // K: 64 rows x 32 chunks
        int idx = tid + k * 512;
        int r = idx >> 5, ch = idx & 31;
        cp16(base + EN_K + r * EK_ROW + ch * 16,
             g_k + ((size_t)b * CQ_ + r) * N_ + j0 + ch * 8);
    }
    CP_COMMIT();
    CP_WAIT(0);
    __syncthreads();

    float acc[2][8][4];
#pragma unroll
    for (int mt = 0; mt < 2; mt++)
#pragma unroll
        for (int t = 0; t < 8; t++)
#pragma unroll
            for (int q = 0; q < 4; q++) acc[mt][t][q] = 0.f;

    const uint32_t aq_row = (uint32_t)((lane & 7) | ((lane >> 4) << 3));
    const uint32_t aq_col = (uint32_t)((warp_m * 32 + ((lane >> 3) & 1) * 8) * 2);
    const uint32_t bk_row = (uint32_t)((lane & 7) | (lane & 8));
    const uint32_t bk_col = (uint32_t)((warp_n * 64 + ((lane >> 4) & 1) * 8) * 2);

#pragma unroll
    for (int ks = 0; ks < 4; ks++) {
        uint32_t ah[2][4];
#pragma unroll
        for (int mt = 0; mt < 2; mt++) {
            uint32_t aoff = (aq_row + ks * 16) * EQ_ROW + aq_col + mt * 32;
            ldm_x4t(ah[mt], base + EN_Q + aoff);
        }
#pragma unroll
        for (int ng = 0; ng < 4; ng++) {
            uint32_t boff = (bk_row + ks * 16) * EK_ROW + bk_col + ng * 32;
            uint32_t bh[4];
            ldm_x4t(bh, base + EN_K + boff);
#pragma unroll
            for (int mt = 0; mt < 2; mt++)
#pragma unroll
                for (int sub = 0; sub < 2; sub++) {
                    float* a = acc[mt][ng * 2 + sub];
                    uint32_t p0 = sub ? bh[2] : bh[0], p1 = sub ? bh[3] : bh[1];
                    mma16816(a, ah[mt], p0, p1);
                }
        }
    }

    // epilogue: exp -> smem staging, rowsums in regs
    const int gp = lane >> 2, tg = lane & 3;
    float rs[2][2] = {{0.f, 0.f}, {0.f, 0.f}};
#pragma unroll
    for (int mt = 0; mt < 2; mt++) {
        const int il = warp_m * 32 + mt * 16 + gp;
#pragma unroll
        for (int t = 0; t < 8; t++) {
            const int jw = warp_n * 32 + t * 4 + tg;
            float e0 = __expf(acc[mt][t][0] * SCALE_);
            float e1 = __expf(acc[mt][t][1] * SCALE_);
            float e2 = __expf(acc[mt][t][2] * SCALE_);
            float e3 = __expf(acc[mt][t][3] * SCALE_);
            rs[mt][0] += e0 + e1;
            rs[mt][1] += e2 + e3;
            pstg[il * EN_STG_STRIDE + jw]       = pack2f(e0, e1);
            pstg[(il + 8) * EN_STG_STRIDE + jw] = pack2f(e2, e3);
        }
    }
#pragma unroll
    for (int mt = 0; mt < 2; mt++)
#pragma unroll
        for (int h = 0; h < 2; h++) {
            float s = rs[mt][h];
            s += __shfl_xor_sync(0xFFFFFFFF, s, 1);
            s += __shfl_xor_sync(0xFFFFFFFF, s, 2);
            if (tg == 0)
                ps[warp_n * 128 + warp_m * 32 + mt * 16 + h * 8 + gp] = s;
        }
    __syncthreads();

    if (tid < 128)
        g_psum[((size_t)b * 16 + jt) * N_ + i0 + tid] =
            ps[tid] + ps[128 + tid] + ps[256 + tid] + ps[384 + tid];

    // coalesced store: warp wid handles rows wid*8 .. wid*8+7
#pragma unroll
    for (int r = 0; r < 8; r++) {
        const int row = wid * 8 + r;
        uint4 v = *(uint4*)(pstg + row * EN_STG_STRIDE + lane * 4);
        *(uint4*)(g_p + ((size_t)b * N_ + i0 + row) * N_ + j0 + lane * 8) = v;
    }
}

// ---------------------------------------------------------------------------
__global__ __launch_bounds__(256) void rowsum_reduce_kernel(int b0)
{
    const int r = b0 * N_ + blockIdx.x * 256 + threadIdx.x;
    const int b = r >> 12, i = r & (N_ - 1);
    float s = 0.f;
#pragma unroll
    for (int jt = 0; jt < 16; jt++)
        s += g_psum[((size_t)b * 16 + jt) * N_ + i];
    g_inv[r] = 1.f / s;
}

// ---------------------------------------------------------------------------
// Output GEMM (512 thr). b = b0 + z.
// ---------------------------------------------------------------------------
#define OUT_ROW 144
#define OUT_A 0
#define OUT_B (128 * OUT_ROW)                      // 18432
#define OUT_STAGE (128 * OUT_ROW + 256 * OUT_ROW)  // 55296
#define OUT_INV (4 * OUT_STAGE)                    // 221184
#define OUT_SMEM (4 * OUT_STAGE + 1024 + 1024)     // 223232
#define OST 260                                    // epilogue fp32 row stride (1040B)

__device__ __forceinline__ void out_load_stage(uint32_t sb, int b, int c0, int i0, int j0, int tid)
{
#pragma unroll
    for (int k = 0; k < 2; k++) {          // A: 128 rows x 8 chunks
        int idx = tid + k * 512;
        int row = idx >> 3, ch = idx & 7;
        cp16(sb + OUT_A + row * OUT_ROW + ch * 16,
             g_v + ((size_t)(b * C_ + c0 + row)) * N_ + j0 + ch * 8);
    }
#pragma unroll
    for (int k = 0; k < 4; k++) {          // B: 256 rows x 8 chunks
        int idx = tid + k * 512;
        int row = idx >> 3, ch = idx & 7;
        cp16(sb + OUT_B + row * OUT_ROW + ch * 16,
             g_p + ((size_t)b * N_ + i0 + row) * N_ + j0 + ch * 8);
    }
    CP_COMMIT();
}

__global__ __launch_bounds__(512, 1) void out_mma_kernel(
    const float* __restrict__ xs, const float* __restrict__ xt,
    float* __restrict__ out, int b0)
{
    extern __shared__ char dsm[];
    uint32_t raw  = smem_u32(dsm);
    uint32_t base = (raw + 1023) & ~1023u;
    char* cbase = dsm + (base - raw);
    float* inv_s = (float*)(cbase + OUT_INV);
    float* stg   = (float*)(cbase);      // epilogue staging (reuses stage 0)

    const int tid = threadIdx.x;
    const int lane = tid & 31;
    const int wid = tid >> 5;
    const int warp_m = wid & 3;      // c: 32 rows
    const int warp_n = wid >> 2;     // i: 64 cols

    const int b  = b0 + blockIdx.z;
    const int c0 = blockIdx.x * 128;
    const int i0 = blockIdx.y * 256;

    float acc[2][8][4];
#pragma unroll
    for (int mt = 0; mt < 2; mt++)
#pragma unroll
        for (int t = 0; t < 8; t++)
#pragma unroll
            for (int q = 0; q < 4; q++) acc[mt][t][q] = 0.f;

    out_load_stage(base,                 b, c0, i0, 0,   tid);
    out_load_stage(base + OUT_STAGE,     b, c0, i0, 64,  tid);
    out_load_stage(base + 2 * OUT_STAGE, b, c0, i0, 128, tid);

    const int lrow = lane & 15;
    const int lkh  = (lane >> 4) * 16;

    for (int chk = 0; chk < 64; chk++) {
        const uint32_t sb = base + (chk & 3) * OUT_STAGE;
        if (chk <= 61)      CP_WAIT(2);
        else if (chk == 62) CP_WAIT(1);
        else                CP_WAIT(0);
        __syncthreads();
        if (chk + 3 < 64)
            out_load_stage(base + ((chk + 3) & 3) * OUT_STAGE, b, c0, i0, (chk + 3) * 64, tid);

        const uint32_t a_base = sb + OUT_A + (warp_m * 32 + lrow) * OUT_ROW + lkh;
        const uint32_t b_base = sb + OUT_B + (warp_n * 64 + lrow) * OUT_ROW + lkh;

#pragma unroll
        for (int ks = 0; ks < 4; ks++) {
            const uint32_t koff = ks * 32;
            uint32_t ah[2][4];
#pragma unroll
            for (int mt = 0; mt < 2; mt++)
                ldm_x4(ah[mt], a_base + mt * (16 * OUT_ROW) + koff);
#pragma unroll
            for (int ng = 0; ng < 4; ng++) {
                uint32_t bh[4];
                ldm_x4(bh, b_base + ng * (16 * OUT_ROW) + koff);
#pragma unroll
                for (int mt = 0; mt < 2; mt++) {
                    mma16816(acc[mt][ng*2],   ah[mt], bh[0], bh[2]);
                    mma16816(acc[mt][ng*2+1], ah[mt], bh[1], bh[3]);
                }
            }
        }
    }

    if (tid < 256) inv_s[tid] = g_inv[b * N_ + i0 + tid];
    __syncthreads();

    // epilogue: 4 slabs of 32 c-rows, staged fp32 transpose, coalesced stores
    const int gp = lane >> 2, tg = lane & 3;
#pragma unroll 1
    for (int s = 0; s < 4; s++) {
        if (warp_m == s) {
#pragma unroll
            for (int mt = 0; mt < 2; mt++) {
                const int cl = mt * 16 + gp;
#pragma unroll
                for (int t = 0; t < 8; t++) {
                    const int iloc = warp_n * 64 + t * 8 + tg * 2;
                    stg[cl * OST + iloc]           = acc[mt][t][0] * inv_s[iloc];
                    stg[cl * OST + iloc + 1]       = acc[mt][t][1] * inv_s[iloc + 1];
                    stg[(cl + 8) * OST + iloc]     = acc[mt][t][2] * inv_s[iloc];
                    stg[(cl + 8) * OST + iloc + 1] = acc[mt][t][3] * inv_s[iloc + 1];
                }
            }
        }
        __syncthreads();
#pragma unroll
        for (int r = 0; r < 2; r++) {
            const int row = wid * 2 + r;
            const size_t gbase = ((size_t)(b * C_ + c0 + s * 32 + row)) * N_ + i0;
#pragma unroll
            for (int it = 0; it < 2; it++) {
                const int f = (it * 32 + lane) * 4;
                float4 o4 = *(float4*)(stg + row * OST + f);
                float4 x1 = *(const float4*)(xs + gbase + f);
                float4 x2 = *(const float4*)(xt + gbase + f);
                o4.x += x1.x + x2.x;
                o4.y += x1.y + x2.y;
                o4.z += x1.z + x2.z;
                o4.w += x1.w + x2.w;
                *(float4*)(out + gbase + f) = o4;
            }
        }
        __syncthreads();
    }
}

// ---------------------------------------------------------------------------
extern "C" void kernel_launch(void* const* d_in, const int* in_sizes, int n_in,
                              void* d_out, int out_size)
{
    const float* xs  = (const float*)d_in[0];
    const float* xt  = (const float*)d_in[1];
    const float* Wq  = (const float*)d_in[2];
    const float* bq  = (const float*)d_in[3];
    const float* Wk  = (const float*)d_in[4];
    const float* bk  = (const float*)d_in[5];
    const float* Wvs = (const float*)d_in[6];
    const float* bvs = (const float*)d_in[7];
    const float* Wvt = (const float*)d_in[8];
    const float* bvt = (const float*)d_in[9];
    float* out = (float*)d_out;

    static cudaStream_t s2 = nullptr, s3 = nullptr;
    static cudaEvent_t ev_fork = nullptr, evR01 = nullptr, evR23 = nullptr;
    static cudaEvent_t evV01 = nullptr, evV23 = nullptr, evO = nullptr;
    if (!s2) {
        cudaFuncSetAttribute(v_proj_mma_kernel, cudaFuncAttributeMaxDynamicSharedMemorySize, VP_SMEM);
        cudaFuncSetAttribute(energy_exp_kernel, cudaFuncAttributeMaxDynamicSharedMemorySize, EN_SMEM);
        cudaFuncSetAttribute(out_mma_kernel,   cudaFuncAttributeMaxDynamicSharedMemorySize, OUT_SMEM);
        cudaStreamCreateWithFlags(&s2, cudaStreamNonBlocking);
        cudaStreamCreateWithFlags(&s3, cudaStreamNonBlocking);
        cudaEventCreateWithFlags(&ev_fork, cudaEventDisableTiming);
        cudaEventCreateWithFlags(&evR01, cudaEventDisableTiming);
        cudaEventCreateWithFlags(&evR23, cudaEventDisableTiming);
        cudaEventCreateWithFlags(&evV01, cudaEventDisableTiming);
        cudaEventCreateWithFlags(&evV23, cudaEventDisableTiming);
        cudaEventCreateWithFlags(&evO, cudaEventDisableTiming);
    }

    w_cvt_kernel<<<dim3(C_ * C_ / 1024, 2), 256>>>(Wvs, Wvt);
    qk_proj_kernel<<<dim3(N_ / 128, B_, 2), 256>>>(Wq, bq, Wk, bk, xs, xt);

    // fork after qk: s2 = energy/rowsum halves, default = v_proj halves
    cudaEventRecord(ev_fork, 0);
    cudaStreamWaitEvent(s2, ev_fork, 0);

    energy_exp_kernel<<<dim3(N_ / 256, N_ / 128, 2), 512, EN_SMEM, s2>>>(0);
    rowsum_reduce_kernel<<<2 * N_ / 256, 256, 0, s2>>>(0);
    cudaEventRecord(evR01, s2);
    energy_exp_kernel<<<dim3(N_ / 256, N_ / 128, 2), 512, EN_SMEM, s2>>>(2);
    rowsum_reduce_kernel<<<2 * N_ / 256, 256, 0, s2>>>(2);
    cudaEventRecord(evR23, s2);

    v_proj_mma_kernel<<<dim3(N_ / 256, C_ / 128, 2), 512, VP_SMEM>>>(bvs, bvt, 0);
    cudaEventRecord(evV01, 0);
    v_proj_mma_kernel<<<dim3(N_ / 256, C_ / 128, 2), 512, VP_SMEM>>>(bvs, bvt, 2);
    cudaEventRecord(evV23, 0);

    // s3: out halves, each gated on its V and rowsum halves
    cudaStreamWaitEvent(s3, evV01, 0);
    cudaStreamWaitEvent(s3, evR01, 0);
    out_mma_kernel<<<dim3(C_ / 128, N_ / 256, 2), 512, OUT_SMEM, s3>>>(xs, xt, out, 0);
    cudaStreamWaitEvent(s3, evV23, 0);
    cudaStreamWaitEvent(s3, evR23, 0);
    out_mma_kernel<<<dim3(C_ / 128, N_ / 256, 2), 512, OUT_SMEM, s3>>>(xs, xt, out, 2);
    cudaEventRecord(evO, s3);

    // join everything back to the capture stream
    cudaStreamWaitEvent(0, evO, 0);
}